// round 6
// baseline (speedup 1.0000x reference)
#include <cuda_runtime.h>
#include <math_constants.h>

#define NB    4
#define MSEQ  2048
#define CDIM  512
#define HNUM  8
#define DHEAD 64
#define TOPK  16
#define BH    (NB * HNUM)   // 32 head-batches

// ---------------- scratch (static device globals; no allocation) ----------------
__device__ float g_xp[NB * MSEQ * CDIM];     // conv+residual output (16 MB)
__device__ float g_q[BH * MSEQ * DHEAD];     // per-head Q (16 MB)
__device__ float g_k[BH * MSEQ * DHEAD];     // per-head K
__device__ float g_v[BH * MSEQ * DHEAD];     // per-head V
__device__ float g_attn[NB * MSEQ * CDIM];   // attention output, (n,m,c) layout

// ---------------- packed f32x2 helpers (FFMA2: 2x fp32 throughput, sm_103a) ----
__device__ __forceinline__ unsigned long long ffma2(unsigned long long a,
                                                    unsigned long long b,
                                                    unsigned long long c) {
    unsigned long long d;
    asm("fma.rn.f32x2 %0, %1, %2, %3;" : "=l"(d) : "l"(a), "l"(b), "l"(c));
    return d;
}
__device__ __forceinline__ unsigned long long fadd2(unsigned long long a,
                                                    unsigned long long b) {
    unsigned long long d;
    asm("add.rn.f32x2 %0, %1, %2;" : "=l"(d) : "l"(a), "l"(b));
    return d;
}
__device__ __forceinline__ unsigned long long pack2(float lo, float hi) {
    unsigned long long r;
    asm("mov.b64 %0, {%1, %2};" : "=l"(r) : "f"(lo), "f"(hi));
    return r;
}
__device__ __forceinline__ unsigned long long dup2(float a) {
    unsigned long long r;
    asm("mov.b64 %0, {%1, %1};" : "=l"(r) : "f"(a));
    return r;
}
__device__ __forceinline__ float2 unpack2(unsigned long long v) {
    float2 f;
    asm("mov.b64 {%0, %1}, %2;" : "=f"(f.x), "=f"(f.y) : "l"(v));
    return f;
}

// ---------------- K1: depthwise conv (k=3, SAME, cross-correlation) + residual --
__global__ void conv_res_kernel(const float* __restrict__ x,
                                const float* __restrict__ w,
                                const float* __restrict__ b) {
    int c = threadIdx.x;                 // 512 channels
    int m = blockIdx.x & (MSEQ - 1);
    int n = blockIdx.x >> 11;
    const float* base = x + ((size_t)(n * MSEQ + m)) * CDIM + c;
    float xc = base[0];
    float xl = (m > 0)        ? base[-CDIM] : 0.f;
    float xr = (m < MSEQ - 1) ? base[ CDIM] : 0.f;
    float w0 = w[3 * c], w1 = w[3 * c + 1], w2 = w[3 * c + 2];
    g_xp[((size_t)(n * MSEQ + m)) * CDIM + c] =
        xc + w0 * xl + w1 * xc + w2 * xr + b[c];
}

// ---------------- K2/K4: SGEMM 128x128x16 tiles, 8x8/thread, f32x2 inner -------
// MODE 0: A = g_xp (8192 x 512), B = w_qkv (512 x 1536); scatter to g_q/g_k/g_v
//         in head layout with bias.
// MODE 1: A = g_attn (8192 x 512), B = w_o (512 x 512); write Cout with bias.
template <int MODE>
__global__ void __launch_bounds__(256) sgemm_kernel(const float* __restrict__ B,
                                                    const float* __restrict__ bias,
                                                    float* __restrict__ Cout) {
    constexpr int NDIM = (MODE == 0) ? 3 * CDIM : CDIM;
    const float* A = (MODE == 0) ? g_xp : g_attn;

    __shared__ __align__(16) float As[16][128];
    __shared__ __align__(16) float Bs[16][128];

    int tid = threadIdx.x;
    int bm = blockIdx.y, bn = blockIdx.x;
    int rowBase = (tid >> 4) << 3;   // 0..120
    int colBase = (tid & 15) << 3;   // 0..120

    unsigned long long acc[8][4];
#pragma unroll
    for (int i = 0; i < 8; i++)
#pragma unroll
        for (int j = 0; j < 4; j++) acc[i][j] = 0ull;

    for (int kt = 0; kt < CDIM / 16; kt++) {
#pragma unroll
        for (int l = 0; l < 2; l++) {
            int fid = tid + l * 256;
            int ar = fid >> 2, ak = (fid & 3) << 2;
            float4 av = *(const float4*)(A + ((size_t)(bm * 128 + ar)) * CDIM +
                                         kt * 16 + ak);
            As[ak + 0][ar] = av.x; As[ak + 1][ar] = av.y;
            As[ak + 2][ar] = av.z; As[ak + 3][ar] = av.w;
            int br = fid >> 5, bc = (fid & 31) << 2;
            *(float4*)&Bs[br][bc] =
                *(const float4*)(B + ((size_t)(kt * 16 + br)) * NDIM +
                                 bn * 128 + bc);
        }
        __syncthreads();
#pragma unroll
        for (int k = 0; k < 16; k++) {
            float4 a0 = *(const float4*)&As[k][rowBase];
            float4 a1 = *(const float4*)&As[k][rowBase + 4];
            ulonglong2 b0 = *(const ulonglong2*)&Bs[k][colBase];
            ulonglong2 b1 = *(const ulonglong2*)&Bs[k][colBase + 4];
            float af[8] = {a0.x, a0.y, a0.z, a0.w, a1.x, a1.y, a1.z, a1.w};
#pragma unroll
            for (int i = 0; i < 8; i++) {
                unsigned long long aa = dup2(af[i]);
                acc[i][0] = ffma2(aa, b0.x, acc[i][0]);
                acc[i][1] = ffma2(aa, b0.y, acc[i][1]);
                acc[i][2] = ffma2(aa, b1.x, acc[i][2]);
                acc[i][3] = ffma2(aa, b1.y, acc[i][3]);
            }
        }
        __syncthreads();
    }

    int co0 = bn * 128 + colBase;
    float bv[8];
#pragma unroll
    for (int j = 0; j < 8; j++) bv[j] = bias[co0 + j];

    if (MODE == 1) {
#pragma unroll
        for (int i = 0; i < 8; i++) {
            int r = bm * 128 + rowBase + i;
            float* dst = Cout + (size_t)r * NDIM + co0;
            float2 p0 = unpack2(acc[i][0]), p1 = unpack2(acc[i][1]);
            float2 p2 = unpack2(acc[i][2]), p3 = unpack2(acc[i][3]);
            float4 lo = make_float4(p0.x + bv[0], p0.y + bv[1],
                                    p1.x + bv[2], p1.y + bv[3]);
            float4 hi = make_float4(p2.x + bv[4], p2.y + bv[5],
                                    p3.x + bv[6], p3.y + bv[7]);
            *(float4*)dst = lo;
            *(float4*)(dst + 4) = hi;
        }
    } else {
        // co0 is 8-aligned -> all 8 columns in one section & one head
        int sec = co0 >> 9;            // 0:q 1:k 2:v
        int c2 = co0 & 511;
        int h = c2 >> 6, dd = c2 & 63; // dd is 8-aligned
        float* dstbuf = (sec == 0) ? g_q : (sec == 1) ? g_k : g_v;
#pragma unroll
        for (int i = 0; i < 8; i++) {
            int r = bm * 128 + rowBase + i;
            int n = r >> 11, mm = r & 2047;
            float* dst = dstbuf +
                ((size_t)((n * HNUM + h) * MSEQ + mm)) * DHEAD + dd;
            float2 p0 = unpack2(acc[i][0]), p1 = unpack2(acc[i][1]);
            float2 p2 = unpack2(acc[i][2]), p3 = unpack2(acc[i][3]);
            float4 lo = make_float4(p0.x + bv[0], p0.y + bv[1],
                                    p1.x + bv[2], p1.y + bv[3]);
            float4 hi = make_float4(p2.x + bv[4], p2.y + bv[5],
                                    p3.x + bv[6], p3.y + bv[7]);
            *(float4*)dst = lo;
            *(float4*)(dst + 4) = hi;
        }
    }
}

// ---------------- K3: routing logits + running top-16 + 16-wide attention ------
// One thread = one query. Key tiles of 64 rows in SMEM; all lanes broadcast-read
// the same key row (conflict-free). Top-16 kept in registers via fully unrolled
// predicated argmin-replace. Strict '>' keeps lowest index on ties (matches
// lax.top_k tie-breaking with ascending key iteration order).
__global__ void __launch_bounds__(128) route_attn_kernel() {
    __shared__ __align__(16) float ks[64 * DHEAD];   // 16 KB key tile

    int b = blockIdx.x >> 4;           // head-batch 0..31
    int qt = blockIdx.x & 15;
    int tid = threadIdx.x;
    int m = qt * 128 + tid;

    const float scale = 0.04419417382415922f;        // 512^-0.5

    const float* qrow = g_q + ((size_t)(b * MSEQ + m)) * DHEAD;
    unsigned long long qp[32];
#pragma unroll
    for (int d4 = 0; d4 < 16; d4++) {
        float4 t = ((const float4*)qrow)[d4];
        qp[2 * d4]     = pack2(t.x * scale, t.y * scale);
        qp[2 * d4 + 1] = pack2(t.z * scale, t.w * scale);
    }

    float vals[TOPK];
    int   inds[TOPK];
#pragma unroll
    for (int t = 0; t < TOPK; t++) { vals[t] = -CUDART_INF_F; inds[t] = 0; }
    float minv = -CUDART_INF_F;

    const float* kbase = g_k + (size_t)b * MSEQ * DHEAD;
    for (int kt = 0; kt < MSEQ / 64; kt++) {
        const float4* src = (const float4*)(kbase + (size_t)kt * 64 * DHEAD);
#pragma unroll
        for (int u = 0; u < 8; u++)
            ((float4*)ks)[tid + u * 128] = src[tid + u * 128];
        __syncthreads();

#pragma unroll 4
        for (int j = 0; j < 64; j++) {
            const ulonglong2* kr = (const ulonglong2*)(ks + j * DHEAD);
            unsigned long long a0 = 0ull, a1 = 0ull, a2 = 0ull, a3 = 0ull;
#pragma unroll
            for (int p = 0; p < 16; p += 2) {
                ulonglong2 kv0 = kr[p];
                ulonglong2 kv1 = kr[p + 1];
                a0 = ffma2(qp[2 * p],     kv0.x, a0);
                a1 = ffma2(qp[2 * p + 1], kv0.y, a1);
                a2 = ffma2(qp[2 * p + 2], kv1.x, a2);
                a3 = ffma2(qp[2 * p + 3], kv1.y, a3);
            }
            a0 = fadd2(a0, a1);
            a2 = fadd2(a2, a3);
            a0 = fadd2(a0, a2);
            float2 f = unpack2(a0);
            float s = f.x + f.y;

            if (s > minv) {
                int key = kt * 64 + j;
                float mv = vals[0]; int am = 0;
#pragma unroll
                for (int t = 1; t < TOPK; t++)
                    if (vals[t] < mv) { mv = vals[t]; am = t; }
#pragma unroll
                for (int t = 0; t < TOPK; t++)
                    if (t == am) { vals[t] = s; inds[t] = key; }
                mv = vals[0];
#pragma unroll
                for (int t = 1; t < TOPK; t++) mv = fminf(mv, vals[t]);
                minv = mv;
            }
        }
        __syncthreads();
    }

    // softmax over the 16 kept logits (== aw in the reference)
    float mx = vals[0];
#pragma unroll
    for (int t = 1; t < TOPK; t++) mx = fmaxf(mx, vals[t]);
    float w[TOPK];
    float sum = 0.f;
#pragma unroll
    for (int t = 0; t < TOPK; t++) { w[t] = expf(vals[t] - mx); sum += w[t]; }
    float inv = 1.f / sum;

    float4 o[16];
#pragma unroll
    for (int d4 = 0; d4 < 16; d4++) o[d4] = make_float4(0.f, 0.f, 0.f, 0.f);

    const float* vbase = g_v + (size_t)b * MSEQ * DHEAD;
#pragma unroll
    for (int t = 0; t < TOPK; t++) {
        float wt = w[t] * inv;
        const float4* vr = (const float4*)(vbase + (size_t)inds[t] * DHEAD);
#pragma unroll
        for (int d4 = 0; d4 < 16; d4++) {
            float4 vv = vr[d4];
            o[d4].x += wt * vv.x; o[d4].y += wt * vv.y;
            o[d4].z += wt * vv.z; o[d4].w += wt * vv.w;
        }
    }

    int n = b >> 3, h = b & 7;
    float* dst = g_attn + ((size_t)(n * MSEQ + m)) * CDIM + h * DHEAD;
#pragma unroll
    for (int d4 = 0; d4 < 16; d4++) ((float4*)dst)[d4] = o[d4];
}

// ---------------- launch ----------------
extern "C" void kernel_launch(void* const* d_in, const int* in_sizes, int n_in,
                              void* d_out, int out_size) {
    (void)in_sizes; (void)n_in; (void)out_size;
    const float* x      = (const float*)d_in[0];
    const float* conv_w = (const float*)d_in[1];
    const float* conv_b = (const float*)d_in[2];
    const float* w_qkv  = (const float*)d_in[3];
    const float* b_qkv  = (const float*)d_in[4];
    const float* w_o    = (const float*)d_in[5];
    const float* b_o    = (const float*)d_in[6];

    conv_res_kernel<<<NB * MSEQ, CDIM>>>(x, conv_w, conv_b);
    sgemm_kernel<0><<<dim3(12, 64), 256>>>(w_qkv, b_qkv, nullptr);
    route_attn_kernel<<<BH * 16, 128>>>();
    sgemm_kernel<1><<<dim3(4, 64), 256>>>(w_o, b_o, (float*)d_out);
}

// round 7
// speedup vs baseline: 1.1769x; 1.1769x over previous
#include <cuda_runtime.h>
#include <math_constants.h>

#define NB    4
#define MSEQ  2048
#define CDIM  512
#define HNUM  8
#define DHEAD 64
#define TOPK  16
#define BH    (NB * HNUM)   // 32 head-batches
#define KSPLIT 2
#define KHALF  (MSEQ / KSPLIT)  // 1024

// ---------------- scratch (static device globals; no allocation) ----------------
__device__ float g_xp[NB * MSEQ * CDIM];     // conv+residual output (16 MB)
__device__ float g_q[BH * MSEQ * DHEAD];     // per-head Q
__device__ float g_k[BH * MSEQ * DHEAD];     // per-head K
__device__ float g_v[BH * MSEQ * DHEAD];     // per-head V
__device__ float g_attn[NB * MSEQ * CDIM];   // attention output, (n,m,c) layout
__device__ float g_pvals[BH * MSEQ * KSPLIT * TOPK];  // partial top-k vals (sorted asc)
__device__ int   g_pinds[BH * MSEQ * KSPLIT * TOPK];  // partial top-k global key idx

// ---------------- packed f32x2 helpers (FFMA2: 2x fp32 throughput, sm_103a) ----
__device__ __forceinline__ unsigned long long ffma2(unsigned long long a,
                                                    unsigned long long b,
                                                    unsigned long long c) {
    unsigned long long d;
    asm("fma.rn.f32x2 %0, %1, %2, %3;" : "=l"(d) : "l"(a), "l"(b), "l"(c));
    return d;
}
__device__ __forceinline__ unsigned long long fadd2(unsigned long long a,
                                                    unsigned long long b) {
    unsigned long long d;
    asm("add.rn.f32x2 %0, %1, %2;" : "=l"(d) : "l"(a), "l"(b));
    return d;
}
__device__ __forceinline__ unsigned long long pack2(float lo, float hi) {
    unsigned long long r;
    asm("mov.b64 %0, {%1, %2};" : "=l"(r) : "f"(lo), "f"(hi));
    return r;
}
__device__ __forceinline__ unsigned long long dup2(float a) {
    unsigned long long r;
    asm("mov.b64 %0, {%1, %1};" : "=l"(r) : "f"(a));
    return r;
}
__device__ __forceinline__ float2 unpack2(unsigned long long v) {
    float2 f;
    asm("mov.b64 {%0, %1}, %2;" : "=f"(f.x), "=f"(f.y) : "l"(v));
    return f;
}

// ---------------- K1: depthwise conv (k=3, SAME) + residual --------------------
__global__ void conv_res_kernel(const float* __restrict__ x,
                                const float* __restrict__ w,
                                const float* __restrict__ b) {
    int c = threadIdx.x;
    int m = blockIdx.x & (MSEQ - 1);
    int n = blockIdx.x >> 11;
    const float* base = x + ((size_t)(n * MSEQ + m)) * CDIM + c;
    float xc = base[0];
    float xl = (m > 0)        ? base[-CDIM] : 0.f;
    float xr = (m < MSEQ - 1) ? base[ CDIM] : 0.f;
    float w0 = w[3 * c], w1 = w[3 * c + 1], w2 = w[3 * c + 2];
    g_xp[((size_t)(n * MSEQ + m)) * CDIM + c] =
        xc + w0 * xl + w1 * xc + w2 * xr + b[c];
}

// ---------------- K2: QKV GEMM, 128x128 tiles, double-buffered -----------------
// A = g_xp (8192 x 512), B = w_qkv (512 x 1536). Scatter to g_q/g_k/g_v + bias.
__global__ void __launch_bounds__(256) sgemm_qkv_kernel(const float* __restrict__ B,
                                                        const float* __restrict__ bias) {
    constexpr int NDIM = 3 * CDIM;
    __shared__ __align__(16) float As[2][16][128];
    __shared__ __align__(16) float Bs[2][16][128];

    int tid = threadIdx.x;
    int bm = blockIdx.y, bn = blockIdx.x;
    int rowBase = (tid >> 4) << 3;
    int colBase = (tid & 15) << 3;

    int ar = tid >> 2, ak = (tid & 3) << 2;      // A loader: rows ar, ar+64
    int br = tid >> 5, bc = (tid & 31) << 2;     // B loader: rows br, br+8

    const float* Ap = g_xp + ((size_t)(bm * 128)) * CDIM;
    const float* Bp = B + bn * 128;

    // prologue: fetch k-tile 0
    float4 a0 = *(const float4*)(Ap + (size_t)ar * CDIM + ak);
    float4 a1 = *(const float4*)(Ap + (size_t)(ar + 64) * CDIM + ak);
    float4 b0 = *(const float4*)(Bp + (size_t)br * NDIM + bc);
    float4 b1 = *(const float4*)(Bp + (size_t)(br + 8) * NDIM + bc);

    As[0][ak + 0][ar] = a0.x; As[0][ak + 1][ar] = a0.y;
    As[0][ak + 2][ar] = a0.z; As[0][ak + 3][ar] = a0.w;
    As[0][ak + 0][ar + 64] = a1.x; As[0][ak + 1][ar + 64] = a1.y;
    As[0][ak + 2][ar + 64] = a1.z; As[0][ak + 3][ar + 64] = a1.w;
    *(float4*)&Bs[0][br][bc] = b0;
    *(float4*)&Bs[0][br + 8][bc] = b1;
    __syncthreads();

    unsigned long long acc[8][4];
#pragma unroll
    for (int i = 0; i < 8; i++)
#pragma unroll
        for (int j = 0; j < 4; j++) acc[i][j] = 0ull;

#pragma unroll 1
    for (int kt = 0; kt < 31; kt++) {
        int cur = kt & 1, nxt = cur ^ 1;
        // prefetch next k-tile
        const float* Ak = Ap + (kt + 1) * 16;
        a0 = *(const float4*)(Ak + (size_t)ar * CDIM + ak);
        a1 = *(const float4*)(Ak + (size_t)(ar + 64) * CDIM + ak);
        const float* Bk = Bp + (size_t)((kt + 1) * 16) * NDIM;
        b0 = *(const float4*)(Bk + (size_t)br * NDIM + bc);
        b1 = *(const float4*)(Bk + (size_t)(br + 8) * NDIM + bc);

#pragma unroll
        for (int k = 0; k < 16; k++) {
            float4 av0 = *(const float4*)&As[cur][k][rowBase];
            float4 av1 = *(const float4*)&As[cur][k][rowBase + 4];
            ulonglong2 bv0 = *(const ulonglong2*)&Bs[cur][k][colBase];
            ulonglong2 bv1 = *(const ulonglong2*)&Bs[cur][k][colBase + 4];
            float af[8] = {av0.x, av0.y, av0.z, av0.w, av1.x, av1.y, av1.z, av1.w};
#pragma unroll
            for (int i = 0; i < 8; i++) {
                unsigned long long aa = dup2(af[i]);
                acc[i][0] = ffma2(aa, bv0.x, acc[i][0]);
                acc[i][1] = ffma2(aa, bv0.y, acc[i][1]);
                acc[i][2] = ffma2(aa, bv1.x, acc[i][2]);
                acc[i][3] = ffma2(aa, bv1.y, acc[i][3]);
            }
        }
        As[nxt][ak + 0][ar] = a0.x; As[nxt][ak + 1][ar] = a0.y;
        As[nxt][ak + 2][ar] = a0.z; As[nxt][ak + 3][ar] = a0.w;
        As[nxt][ak + 0][ar + 64] = a1.x; As[nxt][ak + 1][ar + 64] = a1.y;
        As[nxt][ak + 2][ar + 64] = a1.z; As[nxt][ak + 3][ar + 64] = a1.w;
        *(float4*)&Bs[nxt][br][bc] = b0;
        *(float4*)&Bs[nxt][br + 8][bc] = b1;
        __syncthreads();
    }
    // final tile (buffer 1)
#pragma unroll
    for (int k = 0; k < 16; k++) {
        float4 av0 = *(const float4*)&As[1][k][rowBase];
        float4 av1 = *(const float4*)&As[1][k][rowBase + 4];
        ulonglong2 bv0 = *(const ulonglong2*)&Bs[1][k][colBase];
        ulonglong2 bv1 = *(const ulonglong2*)&Bs[1][k][colBase + 4];
        float af[8] = {av0.x, av0.y, av0.z, av0.w, av1.x, av1.y, av1.z, av1.w};
#pragma unroll
        for (int i = 0; i < 8; i++) {
            unsigned long long aa = dup2(af[i]);
            acc[i][0] = ffma2(aa, bv0.x, acc[i][0]);
            acc[i][1] = ffma2(aa, bv0.y, acc[i][1]);
            acc[i][2] = ffma2(aa, bv1.x, acc[i][2]);
            acc[i][3] = ffma2(aa, bv1.y, acc[i][3]);
        }
    }

    int co0 = bn * 128 + colBase;
    float bv[8];
#pragma unroll
    for (int j = 0; j < 8; j++) bv[j] = bias[co0 + j];

    // co0 8-aligned -> all 8 columns in one section & head
    int sec = co0 >> 9;            // 0:q 1:k 2:v
    int c2 = co0 & 511;
    int h = c2 >> 6, dd = c2 & 63;
    float* dstbuf = (sec == 0) ? g_q : (sec == 1) ? g_k : g_v;
#pragma unroll
    for (int i = 0; i < 8; i++) {
        int r = bm * 128 + rowBase + i;
        int n = r >> 11, mm = r & 2047;
        float* dst = dstbuf + ((size_t)((n * HNUM + h) * MSEQ + mm)) * DHEAD + dd;
        float2 p0 = unpack2(acc[i][0]), p1 = unpack2(acc[i][1]);
        float2 p2 = unpack2(acc[i][2]), p3 = unpack2(acc[i][3]);
        *(float4*)dst = make_float4(p0.x + bv[0], p0.y + bv[1],
                                    p1.x + bv[2], p1.y + bv[3]);
        *(float4*)(dst + 4) = make_float4(p2.x + bv[4], p2.y + bv[5],
                                          p3.x + bv[6], p3.y + bv[7]);
    }
}

// ---------------- sorted top-16 parallel shift-insert --------------------------
// vals ascending; vals[0] is the running 16th-largest. All 16 lanes of the shift
// are independent compare+selects (latency ~12 cyc vs ~220 for the serial scan).
// Strict '<' keeps earlier (lower-index) keys on ties, matching lax.top_k.
__device__ __forceinline__ void topk_insert(float (&vals)[TOPK], int (&inds)[TOPK],
                                            float s, int key) {
    bool c[TOPK];
#pragma unroll
    for (int t = 0; t < TOPK; t++) c[t] = vals[t] < s;
#pragma unroll
    for (int t = 0; t < TOPK - 1; t++) {
        vals[t] = c[t + 1] ? vals[t + 1] : (c[t] ? s : vals[t]);
        inds[t] = c[t + 1] ? inds[t + 1] : (c[t] ? key : inds[t]);
    }
    vals[TOPK - 1] = c[TOPK - 1] ? s : vals[TOPK - 1];
    inds[TOPK - 1] = c[TOPK - 1] ? key : inds[TOPK - 1];
}

// ---------------- K3a: routing logits + partial top-16 (split-K over keys) -----
// One thread = one query; each block covers 1024 of the 2048 keys.
// 4 keys per branch: deep FFMA2 ILP, 4x fewer BSSY/BSYNC.
__global__ void __launch_bounds__(128) route_part_kernel() {
    __shared__ __align__(16) float ks[64 * DHEAD];   // 16 KB key tile

    int bx = blockIdx.x;
    int b   = bx >> 5;          // head-batch 0..31
    int ksp = (bx >> 4) & 1;    // key split 0/1
    int qt  = bx & 15;          // query tile
    int tid = threadIdx.x;
    int m = qt * 128 + tid;

    const float scale = 0.04419417382415922f;        // 512^-0.5

    const float* qrow = g_q + ((size_t)(b * MSEQ + m)) * DHEAD;
    unsigned long long qp[32];
#pragma unroll
    for (int d4 = 0; d4 < 16; d4++) {
        float4 t = ((const float4*)qrow)[d4];
        qp[2 * d4]     = pack2(t.x * scale, t.y * scale);
        qp[2 * d4 + 1] = pack2(t.z * scale, t.w * scale);
    }

    float vals[TOPK];
    int   inds[TOPK];
#pragma unroll
    for (int t = 0; t < TOPK; t++) { vals[t] = -CUDART_INF_F; inds[t] = 0; }

    const float* kbase = g_k + (size_t)b * MSEQ * DHEAD + (size_t)ksp * KHALF * DHEAD;

    for (int kt = 0; kt < KHALF / 64; kt++) {
        const float4* src = (const float4*)(kbase + (size_t)kt * 64 * DHEAD);
#pragma unroll
        for (int u = 0; u < 8; u++)
            ((float4*)ks)[tid + u * 128] = src[tid + u * 128];
        __syncthreads();

#pragma unroll 1
        for (int j = 0; j < 64; j += 4) {
            const ulonglong2* kr0 = (const ulonglong2*)(ks + (j + 0) * DHEAD);
            const ulonglong2* kr1 = (const ulonglong2*)(ks + (j + 1) * DHEAD);
            const ulonglong2* kr2 = (const ulonglong2*)(ks + (j + 2) * DHEAD);
            const ulonglong2* kr3 = (const ulonglong2*)(ks + (j + 3) * DHEAD);
            unsigned long long a00 = 0ull, a01 = 0ull, a10 = 0ull, a11 = 0ull;
            unsigned long long a20 = 0ull, a21 = 0ull, a30 = 0ull, a31 = 0ull;
#pragma unroll
            for (int p = 0; p < 16; p++) {
                ulonglong2 v0 = kr0[p], v1 = kr1[p], v2 = kr2[p], v3 = kr3[p];
                a00 = ffma2(qp[2 * p],     v0.x, a00);
                a01 = ffma2(qp[2 * p + 1], v0.y, a01);
                a10 = ffma2(qp[2 * p],     v1.x, a10);
                a11 = ffma2(qp[2 * p + 1], v1.y, a11);
                a20 = ffma2(qp[2 * p],     v2.x, a20);
                a21 = ffma2(qp[2 * p + 1], v2.y, a21);
                a30 = ffma2(qp[2 * p],     v3.x, a30);
                a31 = ffma2(qp[2 * p + 1], v3.y, a31);
            }
            float2 f0 = unpack2(fadd2(a00, a01));
            float2 f1 = unpack2(fadd2(a10, a11));
            float2 f2 = unpack2(fadd2(a20, a21));
            float2 f3 = unpack2(fadd2(a30, a31));
            float s0 = f0.x + f0.y, s1 = f1.x + f1.y;
            float s2 = f2.x + f2.y, s3 = f3.x + f3.y;

            float smax = fmaxf(fmaxf(s0, s1), fmaxf(s2, s3));
            if (smax > vals[0]) {
                int key = kt * 64 + j;
                if (s0 > vals[0]) topk_insert(vals, inds, s0, key);
                if (s1 > vals[0]) topk_insert(vals, inds, s1, key + 1);
                if (s2 > vals[0]) topk_insert(vals, inds, s2, key + 2);
                if (s3 > vals[0]) topk_insert(vals, inds, s3, key + 3);
            }
        }
        __syncthreads();
    }

    size_t base = ((size_t)(b * MSEQ + m) * KSPLIT + ksp) * TOPK;
    int koff = ksp * KHALF;
#pragma unroll
    for (int t = 0; t < TOPK; t++) {
        g_pvals[base + t] = vals[t];
        g_pinds[base + t] = inds[t] + koff;   // globalize key index
    }
}

// ---------------- K3b: merge partial top-16s + softmax + V gather --------------
__global__ void __launch_bounds__(128) merge_attn_kernel() {
    int g = blockIdx.x * 128 + threadIdx.x;      // 0..65535 global query
    int b = g >> 11, m = g & 2047;

    size_t base = (size_t)g * (KSPLIT * TOPK);
    float vals[TOPK];
    int   inds[TOPK];
#pragma unroll
    for (int t = 0; t < TOPK; t++) {
        vals[t] = g_pvals[base + t];             // split 0, sorted ascending
        inds[t] = g_pinds[base + t];
    }
    // insert split 1 (lower-index keys live in split 0, so strict '<' keeps them)
#pragma unroll
    for (int t = 0; t < TOPK; t++) {
        float s = g_pvals[base + TOPK + t];
        int   k = g_pinds[base + TOPK + t];
        topk_insert(vals, inds, s, k);
    }

    // softmax over the 16 kept logits
    float mx = vals[TOPK - 1];                   // sorted: last is max
    float w[TOPK];
    float sum = 0.f;
#pragma unroll
    for (int t = 0; t < TOPK; t++) { w[t] = expf(vals[t] - mx); sum += w[t]; }
    float inv = 1.f / sum;

    unsigned long long o[32];
#pragma unroll
    for (int p = 0; p < 32; p++) o[p] = 0ull;

    const float* vbase = g_v + (size_t)b * MSEQ * DHEAD;
#pragma unroll
    for (int t = 0; t < TOPK; t++) {
        unsigned long long wt = dup2(w[t] * inv);
        const ulonglong2* vr = (const ulonglong2*)(vbase + (size_t)inds[t] * DHEAD);
#pragma unroll
        for (int p = 0; p < 16; p++) {
            ulonglong2 vv = vr[p];
            o[2 * p]     = ffma2(wt, vv.x, o[2 * p]);
            o[2 * p + 1] = ffma2(wt, vv.y, o[2 * p + 1]);
        }
    }

    int n = b >> 3, h = b & 7;
    float* dst = g_attn + ((size_t)(n * MSEQ + m)) * CDIM + h * DHEAD;
#pragma unroll
    for (int p = 0; p < 16; p++) {
        ulonglong2 wv; wv.x = o[2 * p]; wv.y = o[2 * p + 1];
        ((ulonglong2*)dst)[p] = wv;
    }
}

// ---------------- K4: output GEMM, 64x128 tiles, double-buffered ---------------
// A = g_attn (8192 x 512), B = w_o (512 x 512) -> Cout + bias.
__global__ void __launch_bounds__(256) sgemm_out_kernel(const float* __restrict__ B,
                                                        const float* __restrict__ bias,
                                                        float* __restrict__ Cout) {
    constexpr int NDIM = CDIM;
    __shared__ __align__(16) float As[2][16][64];
    __shared__ __align__(16) float Bs[2][16][128];

    int tid = threadIdx.x;
    int bm = blockIdx.y, bn = blockIdx.x;
    int rowBase = (tid >> 4) << 2;   // 0..60
    int colBase = (tid & 15) << 3;   // 0..120

    int ar = tid >> 2, ak = (tid & 3) << 2;    // A loader: 1 float4, rows 0..63
    int br = tid >> 5, bc = (tid & 31) << 2;   // B loader: rows br, br+8

    const float* Ap = g_attn + ((size_t)(bm * 64)) * CDIM;
    const float* Bp = B + bn * 128;

    float4 a0 = *(const float4*)(Ap + (size_t)ar * CDIM + ak);
    float4 b0 = *(const float4*)(Bp + (size_t)br * NDIM + bc);
    float4 b1 = *(const float4*)(Bp + (size_t)(br + 8) * NDIM + bc);
    As[0][ak + 0][ar] = a0.x; As[0][ak + 1][ar] = a0.y;
    As[0][ak + 2][ar] = a0.z; As[0][ak + 3][ar] = a0.w;
    *(float4*)&Bs[0][br][bc] = b0;
    *(float4*)&Bs[0][br + 8][bc] = b1;
    __syncthreads();

    unsigned long long acc[4][4];
#pragma unroll
    for (int i = 0; i < 4; i++)
#pragma unroll
        for (int j = 0; j < 4; j++) acc[i][j] = 0ull;

#pragma unroll 1
    for (int kt = 0; kt < 31; kt++) {
        int cur = kt & 1, nxt = cur ^ 1;
        const float* Ak = Ap + (kt + 1) * 16;
        a0 = *(const float4*)(Ak + (size_t)ar * CDIM + ak);
        const float* Bk = Bp + (size_t)((kt + 1) * 16) * NDIM;
        b0 = *(const float4*)(Bk + (size_t)br * NDIM + bc);
        b1 = *(const float4*)(Bk + (size_t)(br + 8) * NDIM + bc);

#pragma unroll
        for (int k = 0; k < 16; k++) {
            float4 av = *(const float4*)&As[cur][k][rowBase];
            ulonglong2 bv0 = *(const ulonglong2*)&Bs[cur][k][colBase];
            ulonglong2 bv1 = *(const ulonglong2*)&Bs[cur][k][colBase + 4];
            float af[4] = {av.x, av.y, av.z, av.w};
#pragma unroll
            for (int i = 0; i < 4; i++) {
                unsigned long long aa = dup2(af[i]);
                acc[i][0] = ffma2(aa, bv0.x, acc[i][0]);
                acc[i][1] = ffma2(aa, bv0.y, acc[i][1]);
                acc[i][2] = ffma2(aa, bv1.x, acc[i][2]);
                acc[i][3] = ffma2(aa, bv1.y, acc[i][3]);
            }
        }
        As[nxt][ak + 0][ar] = a0.x; As[nxt][ak + 1][ar] = a0.y;
        As[nxt][ak + 2][ar] = a0.z; As[nxt][ak + 3][ar] = a0.w;
        *(float4*)&Bs[nxt][br][bc] = b0;
        *(float4*)&Bs[nxt][br + 8][bc] = b1;
        __syncthreads();
    }
#pragma unroll
    for (int k = 0; k < 16; k++) {
        float4 av = *(const float4*)&As[1][k][rowBase];
        ulonglong2 bv0 = *(const ulonglong2*)&Bs[1][k][colBase];
        ulonglong2 bv1 = *(const ulonglong2*)&Bs[1][k][colBase + 4];
        float af[4] = {av.x, av.y, av.z, av.w};
#pragma unroll
        for (int i = 0; i < 4; i++) {
            unsigned long long aa = dup2(af[i]);
            acc[i][0] = ffma2(aa, bv0.x, acc[i][0]);
            acc[i][1] = ffma2(aa, bv0.y, acc[i][1]);
            acc[i][2] = ffma2(aa, bv1.x, acc[i][2]);
            acc[i][3] = ffma2(aa, bv1.y, acc[i][3]);
        }
    }

    int co0 = bn * 128 + colBase;
    float bv[8];
#pragma unroll
    for (int j = 0; j < 8; j++) bv[j] = bias[co0 + j];
#pragma unroll
    for (int i = 0; i < 4; i++) {
        int r = bm * 64 + rowBase + i;
        float* dst = Cout + (size_t)r * NDIM + co0;
        float2 p0 = unpack2(acc[i][0]), p1 = unpack2(acc[i][1]);
        float2 p2 = unpack2(acc[i][2]), p3 = unpack2(acc[i][3]);
        *(float4*)dst = make_float4(p0.x + bv[0], p0.y + bv[1],
                                    p1.x + bv[2], p1.y + bv[3]);
        *(float4*)(dst + 4) = make_float4(p2.x + bv[4], p2.y + bv[5],
                                          p3.x + bv[6], p3.y + bv[7]);
    }
}

// ---------------- launch ----------------
extern "C" void kernel_launch(void* const* d_in, const int* in_sizes, int n_in,
                              void* d_out, int out_size) {
    (void)in_sizes; (void)n_in; (void)out_size;
    const float* x      = (const float*)d_in[0];
    const float* conv_w = (const float*)d_in[1];
    const float* conv_b = (const float*)d_in[2];
    const float* w_qkv  = (const float*)d_in[3];
    const float* b_qkv  = (const float*)d_in[4];
    const float* w_o    = (const float*)d_in[5];
    const float* b_o    = (const float*)d_in[6];

    conv_res_kernel<<<NB * MSEQ, CDIM>>>(x, conv_w, conv_b);
    sgemm_qkv_kernel<<<dim3(12, 64), 256>>>(w_qkv, b_qkv);
    route_part_kernel<<<BH * 16 * KSPLIT, 128>>>();
    merge_attn_kernel<<<512, 128>>>();
    sgemm_out_kernel<<<dim3(4, 128), 256>>>(w_o, b_o, (float*)d_out);
}

// round 11
// speedup vs baseline: 1.2950x; 1.1004x over previous
#include <cuda_runtime.h>
#include <math_constants.h>

#define NB    4
#define MSEQ  2048
#define CDIM  512
#define HNUM  8
#define DHEAD 64
#define TOPK  16
#define BH    (NB * HNUM)   // 32 head-batches
#define KSPLIT 2
#define KHALF  (MSEQ / KSPLIT)  // 1024

// ---------------- scratch (static device globals; no allocation) ----------------
__device__ float g_xp[NB * MSEQ * CDIM];     // conv+residual output (16 MB)
__device__ float g_q[BH * MSEQ * DHEAD];     // per-head Q
__device__ float g_k[BH * MSEQ * DHEAD];     // per-head K
__device__ float g_v[BH * MSEQ * DHEAD];     // per-head V
__device__ float g_attn[NB * MSEQ * CDIM];   // attention output, (n,m,c) layout
__device__ float g_pvals[BH * MSEQ * KSPLIT * TOPK];  // partial top-k vals (sorted asc)
__device__ int   g_pinds[BH * MSEQ * KSPLIT * TOPK];  // partial top-k global key idx

// ---------------- packed f32x2 helpers (FFMA2: 2x fp32 throughput, sm_103a) ----
__device__ __forceinline__ unsigned long long ffma2(unsigned long long a,
                                                    unsigned long long b,
                                                    unsigned long long c) {
    unsigned long long d;
    asm("fma.rn.f32x2 %0, %1, %2, %3;" : "=l"(d) : "l"(a), "l"(b), "l"(c));
    return d;
}
__device__ __forceinline__ unsigned long long fadd2(unsigned long long a,
                                                    unsigned long long b) {
    unsigned long long d;
    asm("add.rn.f32x2 %0, %1, %2;" : "=l"(d) : "l"(a), "l"(b));
    return d;
}
__device__ __forceinline__ unsigned long long pack2(float lo, float hi) {
    unsigned long long r;
    asm("mov.b64 %0, {%1, %2};" : "=l"(r) : "f"(lo), "f"(hi));
    return r;
}
__device__ __forceinline__ unsigned long long dup2(float a) {
    unsigned long long r;
    asm("mov.b64 %0, {%1, %1};" : "=l"(r) : "f"(a));
    return r;
}
__device__ __forceinline__ float2 unpack2(unsigned long long v) {
    float2 f;
    asm("mov.b64 {%0, %1}, %2;" : "=f"(f.x), "=f"(f.y) : "l"(v));
    return f;
}

// ---------------- K1: depthwise conv (k=3, SAME) + residual --------------------
__global__ void conv_res_kernel(const float* __restrict__ x,
                                const float* __restrict__ w,
                                const float* __restrict__ b) {
    int c = threadIdx.x;
    int m = blockIdx.x & (MSEQ - 1);
    int n = blockIdx.x >> 11;
    const float* base = x + ((size_t)(n * MSEQ + m)) * CDIM + c;
    float xc = base[0];
    float xl = (m > 0)        ? base[-CDIM] : 0.f;
    float xr = (m < MSEQ - 1) ? base[ CDIM] : 0.f;
    float w0 = w[3 * c], w1 = w[3 * c + 1], w2 = w[3 * c + 2];
    g_xp[((size_t)(n * MSEQ + m)) * CDIM + c] =
        xc + w0 * xl + w1 * xc + w2 * xr + b[c];
}

// ---------------- K2: QKV GEMM, 128x128 tiles, double-buffered -----------------
__global__ void __launch_bounds__(256) sgemm_qkv_kernel(const float* __restrict__ B,
                                                        const float* __restrict__ bias) {
    constexpr int NDIM = 3 * CDIM;
    __shared__ __align__(16) float As[2][16][128];
    __shared__ __align__(16) float Bs[2][16][128];

    int tid = threadIdx.x;
    int bm = blockIdx.y, bn = blockIdx.x;
    int rowBase = (tid >> 4) << 3;
    int colBase = (tid & 15) << 3;

    int ar = tid >> 2, ak = (tid & 3) << 2;
    int br = tid >> 5, bc = (tid & 31) << 2;

    const float* Ap = g_xp + ((size_t)(bm * 128)) * CDIM;
    const float* Bp = B + bn * 128;

    float4 a0 = *(const float4*)(Ap + (size_t)ar * CDIM + ak);
    float4 a1 = *(const float4*)(Ap + (size_t)(ar + 64) * CDIM + ak);
    float4 b0 = *(const float4*)(Bp + (size_t)br * NDIM + bc);
    float4 b1 = *(const float4*)(Bp + (size_t)(br + 8) * NDIM + bc);

    As[0][ak + 0][ar] = a0.x; As[0][ak + 1][ar] = a0.y;
    As[0][ak + 2][ar] = a0.z; As[0][ak + 3][ar] = a0.w;
    As[0][ak + 0][ar + 64] = a1.x; As[0][ak + 1][ar + 64] = a1.y;
    As[0][ak + 2][ar + 64] = a1.z; As[0][ak + 3][ar + 64] = a1.w;
    *(float4*)&Bs[0][br][bc] = b0;
    *(float4*)&Bs[0][br + 8][bc] = b1;
    __syncthreads();

    unsigned long long acc[8][4];
#pragma unroll
    for (int i = 0; i < 8; i++)
#pragma unroll
        for (int j = 0; j < 4; j++) acc[i][j] = 0ull;

#pragma unroll 1
    for (int kt = 0; kt < 31; kt++) {
        int cur = kt & 1, nxt = cur ^ 1;
        const float* Ak = Ap + (kt + 1) * 16;
        a0 = *(const float4*)(Ak + (size_t)ar * CDIM + ak);
        a1 = *(const float4*)(Ak + (size_t)(ar + 64) * CDIM + ak);
        const float* Bk = Bp + (size_t)((kt + 1) * 16) * NDIM;
        b0 = *(const float4*)(Bk + (size_t)br * NDIM + bc);
        b1 = *(const float4*)(Bk + (size_t)(br + 8) * NDIM + bc);

#pragma unroll
        for (int k = 0; k < 16; k++) {
            float4 av0 = *(const float4*)&As[cur][k][rowBase];
            float4 av1 = *(const float4*)&As[cur][k][rowBase + 4];
            ulonglong2 bv0 = *(const ulonglong2*)&Bs[cur][k][colBase];
            ulonglong2 bv1 = *(const ulonglong2*)&Bs[cur][k][colBase + 4];
            float af[8] = {av0.x, av0.y, av0.z, av0.w, av1.x, av1.y, av1.z, av1.w};
#pragma unroll
            for (int i = 0; i < 8; i++) {
                unsigned long long aa = dup2(af[i]);
                acc[i][0] = ffma2(aa, bv0.x, acc[i][0]);
                acc[i][1] = ffma2(aa, bv0.y, acc[i][1]);
                acc[i][2] = ffma2(aa, bv1.x, acc[i][2]);
                acc[i][3] = ffma2(aa, bv1.y, acc[i][3]);
            }
        }
        As[nxt][ak + 0][ar] = a0.x; As[nxt][ak + 1][ar] = a0.y;
        As[nxt][ak + 2][ar] = a0.z; As[nxt][ak + 3][ar] = a0.w;
        As[nxt][ak + 0][ar + 64] = a1.x; As[nxt][ak + 1][ar + 64] = a1.y;
        As[nxt][ak + 2][ar + 64] = a1.z; As[nxt][ak + 3][ar + 64] = a1.w;
        *(float4*)&Bs[nxt][br][bc] = b0;
        *(float4*)&Bs[nxt][br + 8][bc] = b1;
        __syncthreads();
    }
#pragma unroll
    for (int k = 0; k < 16; k++) {
        float4 av0 = *(const float4*)&As[1][k][rowBase];
        float4 av1 = *(const float4*)&As[1][k][rowBase + 4];
        ulonglong2 bv0 = *(const ulonglong2*)&Bs[1][k][colBase];
        ulonglong2 bv1 = *(const ulonglong2*)&Bs[1][k][colBase + 4];
        float af[8] = {av0.x, av0.y, av0.z, av0.w, av1.x, av1.y, av1.z, av1.w};
#pragma unroll
        for (int i = 0; i < 8; i++) {
            unsigned long long aa = dup2(af[i]);
            acc[i][0] = ffma2(aa, bv0.x, acc[i][0]);
            acc[i][1] = ffma2(aa, bv0.y, acc[i][1]);
            acc[i][2] = ffma2(aa, bv1.x, acc[i][2]);
            acc[i][3] = ffma2(aa, bv1.y, acc[i][3]);
        }
    }

    int co0 = bn * 128 + colBase;
    float bv[8];
#pragma unroll
    for (int j = 0; j < 8; j++) bv[j] = bias[co0 + j];

    int sec = co0 >> 9;            // 0:q 1:k 2:v
    int c2 = co0 & 511;
    int h = c2 >> 6, dd = c2 & 63;
    float* dstbuf = (sec == 0) ? g_q : (sec == 1) ? g_k : g_v;
#pragma unroll
    for (int i = 0; i < 8; i++) {
        int r = bm * 128 + rowBase + i;
        int n = r >> 11, mm = r & 2047;
        float* dst = dstbuf + ((size_t)((n * HNUM + h) * MSEQ + mm)) * DHEAD + dd;
        float2 p0 = unpack2(acc[i][0]), p1 = unpack2(acc[i][1]);
        float2 p2 = unpack2(acc[i][2]), p3 = unpack2(acc[i][3]);
        *(float4*)dst = make_float4(p0.x + bv[0], p0.y + bv[1],
                                    p1.x + bv[2], p1.y + bv[3]);
        *(float4*)(dst + 4) = make_float4(p2.x + bv[4], p2.y + bv[5],
                                          p3.x + bv[6], p3.y + bv[7]);
    }
}

// ---------------- sorted top-16 parallel shift-insert --------------------------
// vals ascending; vals[0] is the running 16th-largest. Strict '<' keeps earlier
// (lower-index) keys on ties, matching lax.top_k.
__device__ __forceinline__ void topk_insert(float (&vals)[TOPK], int (&inds)[TOPK],
                                            float s, int key) {
    bool c[TOPK];
#pragma unroll
    for (int t = 0; t < TOPK; t++) c[t] = vals[t] < s;
#pragma unroll
    for (int t = 0; t < TOPK - 1; t++) {
        vals[t] = c[t + 1] ? vals[t + 1] : (c[t] ? s : vals[t]);
        inds[t] = c[t + 1] ? inds[t + 1] : (c[t] ? key : inds[t]);
    }
    vals[TOPK - 1] = c[TOPK - 1] ? s : vals[TOPK - 1];
    inds[TOPK - 1] = c[TOPK - 1] ? key : inds[TOPK - 1];
}

// ---------------- K3a: routing logits + partial top-16 (split-K over keys) -----
// One thread = one query; each block covers 1024 keys. 4 keys per group with
// k-loads chunked 2 p-steps at a time: only 8 LDS.128 (16 regs) live, keeping
// total demand ~145 regs so __launch_bounds__(128,3) gives 3 blocks/SM with
// NO spills (the round-7 version held ~64 k-regs live -> 1-2 blocks/SM).
__global__ void __launch_bounds__(128, 3) route_part_kernel() {
    __shared__ __align__(16) float ks[64 * DHEAD];   // 16 KB key tile

    int bx = blockIdx.x;
    int b   = bx >> 5;          // head-batch 0..31
    int ksp = (bx >> 4) & 1;    // key split 0/1
    int qt  = bx & 15;          // query tile
    int tid = threadIdx.x;
    int m = qt * 128 + tid;

    const float scale = 0.04419417382415922f;        // 512^-0.5

    const float* qrow = g_q + ((size_t)(b * MSEQ + m)) * DHEAD;
    unsigned long long qp[32];
#pragma unroll
    for (int d4 = 0; d4 < 16; d4++) {
        float4 t = ((const float4*)qrow)[d4];
        qp[2 * d4]     = pack2(t.x * scale, t.y * scale);
        qp[2 * d4 + 1] = pack2(t.z * scale, t.w * scale);
    }

    float vals[TOPK];
    int   inds[TOPK];
#pragma unroll
    for (int t = 0; t < TOPK; t++) { vals[t] = -CUDART_INF_F; inds[t] = 0; }

    const float* kbase = g_k + (size_t)b * MSEQ * DHEAD + (size_t)ksp * KHALF * DHEAD;

    for (int kt = 0; kt < KHALF / 64; kt++) {
        const float4* src = (const float4*)(kbase + (size_t)kt * 64 * DHEAD);
#pragma unroll
        for (int u = 0; u < 8; u++)
            ((float4*)ks)[tid + u * 128] = src[tid + u * 128];
        __syncthreads();

#pragma unroll 1
        for (int j = 0; j < 64; j += 4) {
            const ulonglong2* kr0 = (const ulonglong2*)(ks + (j + 0) * DHEAD);
            const ulonglong2* kr1 = (const ulonglong2*)(ks + (j + 1) * DHEAD);
            const ulonglong2* kr2 = (const ulonglong2*)(ks + (j + 2) * DHEAD);
            const ulonglong2* kr3 = (const ulonglong2*)(ks + (j + 3) * DHEAD);
            unsigned long long a0 = 0ull, a1 = 0ull, a2 = 0ull, a3 = 0ull;
            unsigned long long b0 = 0ull, b1 = 0ull, b2 = 0ull, b3 = 0ull;
            // 8 chunks of 2 p-steps: per chunk 8 LDS.128 live + 16 FFMA2
#pragma unroll
            for (int pc = 0; pc < 16; pc += 2) {
                ulonglong2 k00 = kr0[pc], k01 = kr0[pc + 1];
                ulonglong2 k10 = kr1[pc], k11 = kr1[pc + 1];
                ulonglong2 k20 = kr2[pc], k21 = kr2[pc + 1];
                ulonglong2 k30 = kr3[pc], k31 = kr3[pc + 1];
                unsigned long long q0 = qp[2 * pc],     q1 = qp[2 * pc + 1];
                unsigned long long q2 = qp[2 * pc + 2], q3 = qp[2 * pc + 3];
                a0 = ffma2(q0, k00.x, a0); b0 = ffma2(q1, k00.y, b0);
                a0 = ffma2(q2, k01.x, a0); b0 = ffma2(q3, k01.y, b0);
                a1 = ffma2(q0, k10.x, a1); b1 = ffma2(q1, k10.y, b1);
                a1 = ffma2(q2, k11.x, a1); b1 = ffma2(q3, k11.y, b1);
                a2 = ffma2(q0, k20.x, a2); b2 = ffma2(q1, k20.y, b2);
                a2 = ffma2(q2, k21.x, a2); b2 = ffma2(q3, k21.y, b2);
                a3 = ffma2(q0, k30.x, a3); b3 = ffma2(q1, k30.y, b3);
                a3 = ffma2(q2, k31.x, a3); b3 = ffma2(q3, k31.y, b3);
            }
            float2 f0 = unpack2(fadd2(a0, b0));
            float2 f1 = unpack2(fadd2(a1, b1));
            float2 f2 = unpack2(fadd2(a2, b2));
            float2 f3 = unpack2(fadd2(a3, b3));
            float s0 = f0.x + f0.y, s1 = f1.x + f1.y;
            float s2 = f2.x + f2.y, s3 = f3.x + f3.y;

            float smax = fmaxf(fmaxf(s0, s1), fmaxf(s2, s3));
            if (smax > vals[0]) {
                int key = kt * 64 + j;
                if (s0 > vals[0]) topk_insert(vals, inds, s0, key);
                if (s1 > vals[0]) topk_insert(vals, inds, s1, key + 1);
                if (s2 > vals[0]) topk_insert(vals, inds, s2, key + 2);
                if (s3 > vals[0]) topk_insert(vals, inds, s3, key + 3);
            }
        }
        __syncthreads();
    }

    size_t base = ((size_t)(b * MSEQ + m) * KSPLIT + ksp) * TOPK;
    int koff = ksp * KHALF;
#pragma unroll
    for (int t = 0; t < TOPK; t++) {
        g_pvals[base + t] = vals[t];
        g_pinds[base + t] = inds[t] + koff;   // globalize key index
    }
}

// ---------------- K3b: merge partial top-16s + softmax + V gather --------------
// 4 threads per query. The top-k merge + softmax is computed redundantly by all
// 4 (cheap ALU); the V gather is split: each thread owns a 16-dim slice, giving
// 64 independent LDG.128 per thread and 4x the thread-level parallelism of the
// round-7 version (which sat at occ=17%, issue=5.4%).
__global__ void __launch_bounds__(256) merge_attn_kernel() {
    int tid = threadIdx.x;
    int qloc = tid >> 2, sub = tid & 3;
    int g = blockIdx.x * 64 + qloc;              // global query 0..65535
    int b = g >> 11, m = g & 2047;

    size_t base = (size_t)g * (KSPLIT * TOPK);
    float vals[TOPK];
    int   inds[TOPK];
#pragma unroll
    for (int i = 0; i < 4; i++) {                // split 0, sorted ascending
        float4 v = ((const float4*)(g_pvals + base))[i];
        int4   x = ((const int4*)(g_pinds + base))[i];
        vals[4 * i + 0] = v.x; vals[4 * i + 1] = v.y;
        vals[4 * i + 2] = v.z; vals[4 * i + 3] = v.w;
        inds[4 * i + 0] = x.x; inds[4 * i + 1] = x.y;
        inds[4 * i + 2] = x.z; inds[4 * i + 3] = x.w;
    }
#pragma unroll
    for (int i = 0; i < 4; i++) {                // insert split 1
        float4 v = ((const float4*)(g_pvals + base + TOPK))[i];
        int4   x = ((const int4*)(g_pinds + base + TOPK))[i];
        topk_insert(vals, inds, v.x, x.x);
        topk_insert(vals, inds, v.y, x.y);
        topk_insert(vals, inds, v.z, x.z);
        topk_insert(vals, inds, v.w, x.w);
    }

    float mx = vals[TOPK - 1];                   // sorted: last is max
    float w[TOPK];
    float sum = 0.f;
#pragma unroll
    for (int t = 0; t < TOPK; t++) { w[t] = expf(vals[t] - mx); sum += w[t]; }
    float inv = 1.f / sum;

    // gather: this thread accumulates dims [sub*16, sub*16+16)
    unsigned long long o[8];
#pragma unroll
    for (int p = 0; p < 8; p++) o[p] = 0ull;

    const float* vbase = g_v + (size_t)b * MSEQ * DHEAD + sub * 16;
#pragma unroll
    for (int t = 0; t < TOPK; t++) {
        unsigned long long wt = dup2(w[t] * inv);
        const ulonglong2* vr = (const ulonglong2*)(vbase + (size_t)inds[t] * DHEAD);
#pragma unroll
        for (int p = 0; p < 4; p++) {
            ulonglong2 vv = vr[p];
            o[2 * p]     = ffma2(wt, vv.x, o[2 * p]);
            o[2 * p + 1] = ffma2(wt, vv.y, o[2 * p + 1]);
        }
    }

    int n = b >> 3, h = b & 7;
    float* dst = g_attn + ((size_t)(n * MSEQ + m)) * CDIM + h * DHEAD + sub * 16;
#pragma unroll
    for (int p = 0; p < 4; p++) {
        ulonglong2 wv; wv.x = o[2 * p]; wv.y = o[2 * p + 1];
        ((ulonglong2*)dst)[p] = wv;
    }
}

// ---------------- K4: output GEMM, 64x128 tiles, double-buffered ---------------
__global__ void __launch_bounds__(256) sgemm_out_kernel(const float* __restrict__ B,
                                                        const float* __restrict__ bias,
                                                        float* __restrict__ Cout) {
    constexpr int NDIM = CDIM;
    __shared__ __align__(16) float As[2][16][64];
    __shared__ __align__(16) float Bs[2][16][128];

    int tid = threadIdx.x;
    int bm = blockIdx.y, bn = blockIdx.x;
    int rowBase = (tid >> 4) << 2;
    int colBase = (tid & 15) << 3;

    int ar = tid >> 2, ak = (tid & 3) << 2;
    int br = tid >> 5, bc = (tid & 31) << 2;

    const float* Ap = g_attn + ((size_t)(bm * 64)) * CDIM;
    const float* Bp = B + bn * 128;

    float4 a0 = *(const float4*)(Ap + (size_t)ar * CDIM + ak);
    float4 b0 = *(const float4*)(Bp + (size_t)br * NDIM + bc);
    float4 b1 = *(const float4*)(Bp + (size_t)(br + 8) * NDIM + bc);
    As[0][ak + 0][ar] = a0.x; As[0][ak + 1][ar] = a0.y;
    As[0][ak + 2][ar] = a0.z; As[0][ak + 3][ar] = a0.w;
    *(float4*)&Bs[0][br][bc] = b0;
    *(float4*)&Bs[0][br + 8][bc] = b1;
    __syncthreads();

    unsigned long long acc[4][4];
#pragma unroll
    for (int i = 0; i < 4; i++)
#pragma unroll
        for (int j = 0; j < 4; j++) acc[i][j] = 0ull;

#pragma unroll 1
    for (int kt = 0; kt < 31; kt++) {
        int cur = kt & 1, nxt = cur ^ 1;
        const float* Ak = Ap + (kt + 1) * 16;
        a0 = *(const float4*)(Ak + (size_t)ar * CDIM + ak);
        const float* Bk = Bp + (size_t)((kt + 1) * 16) * NDIM;
        b0 = *(const float4*)(Bk + (size_t)br * NDIM + bc);
        b1 = *(const float4*)(Bk + (size_t)(br + 8) * NDIM + bc);

#pragma unroll
        for (int k = 0; k < 16; k++) {
            float4 av = *(const float4*)&As[cur][k][rowBase];
            ulonglong2 bv0 = *(const ulonglong2*)&Bs[cur][k][colBase];
            ulonglong2 bv1 = *(const ulonglong2*)&Bs[cur][k][colBase + 4];
            float af[4] = {av.x, av.y, av.z, av.w};
#pragma unroll
            for (int i = 0; i < 4; i++) {
                unsigned long long aa = dup2(af[i]);
                acc[i][0] = ffma2(aa, bv0.x, acc[i][0]);
                acc[i][1] = ffma2(aa, bv0.y, acc[i][1]);
                acc[i][2] = ffma2(aa, bv1.x, acc[i][2]);
                acc[i][3] = ffma2(aa, bv1.y, acc[i][3]);
            }
        }
        As[nxt][ak + 0][ar] = a0.x; As[nxt][ak + 1][ar] = a0.y;
        As[nxt][ak + 2][ar] = a0.z; As[nxt][ak + 3][ar] = a0.w;
        *(float4*)&Bs[nxt][br][bc] = b0;
        *(float4*)&Bs[nxt][br + 8][bc] = b1;
        __syncthreads();
    }
#pragma unroll
    for (int k = 0; k < 16; k++) {
        float4 av = *(const float4*)&As[1][k][rowBase];
        ulonglong2 bv0 = *(const ulonglong2*)&Bs[1][k][colBase];
        ulonglong2 bv1 = *(const ulonglong2*)&Bs[1][k][colBase + 4];
        float af[4] = {av.x, av.y, av.z, av.w};
#pragma unroll
        for (int i = 0; i < 4; i++) {
            unsigned long long aa = dup2(af[i]);
            acc[i][0] = ffma2(aa, bv0.x, acc[i][0]);
            acc[i][1] = ffma2(aa, bv0.y, acc[i][1]);
            acc[i][2] = ffma2(aa, bv1.x, acc[i][2]);
            acc[i][3] = ffma2(aa, bv1.y, acc[i][3]);
        }
    }

    int co0 = bn * 128 + colBase;
    float bv[8];
#pragma unroll
    for (int j = 0; j < 8; j++) bv[j] = bias[co0 + j];
#pragma unroll
    for (int i = 0; i < 4; i++) {
        int r = bm * 64 + rowBase + i;
        float* dst = Cout + (size_t)r * NDIM + co0;
        float2 p0 = unpack2(acc[i][0]), p1 = unpack2(acc[i][1]);
        float2 p2 = unpack2(acc[i][2]), p3 = unpack2(acc[i][3]);
        *(float4*)dst = make_float4(p0.x + bv[0], p0.y + bv[1],
                                    p1.x + bv[2], p1.y + bv[3]);
        *(float4*)(dst + 4) = make_float4(p2.x + bv[4], p2.y + bv[5],
                                          p3.x + bv[6], p3.y + bv[7]);
    }
}

// ---------------- launch ----------------
extern "C" void kernel_launch(void* const* d_in, const int* in_sizes, int n_in,
                              void* d_out, int out_size) {
    (void)in_sizes; (void)n_in; (void)out_size;
    const float* x      = (const float*)d_in[0];
    const float* conv_w = (const float*)d_in[1];
    const float* conv_b = (const float*)d_in[2];
    const float* w_qkv  = (const float*)d_in[3];
    const float* b_qkv  = (const float*)d_in[4];
    const float* w_o    = (const float*)d_in[5];
    const float* b_o    = (const float*)d_in[6];

    conv_res_kernel<<<NB * MSEQ, CDIM>>>(x, conv_w, conv_b);
    sgemm_qkv_kernel<<<dim3(12, 64), 256>>>(w_qkv, b_qkv);
    route_part_kernel<<<BH * 16 * KSPLIT, 128>>>();
    merge_attn_kernel<<<1024, 256>>>();
    sgemm_out_kernel<<<dim3(4, 128), 256>>>(w_o, b_o, (float*)d_out);
}